// round 12
// baseline (speedup 1.0000x reference)
#include <cuda_runtime.h>
#include <cuda_bf16.h>
#include <cstdint>
#include <math.h>

#define NN    100000
#define NPAD  100096
#define EE    1600000
#define FIN   27
#define EMB   64
#define HH    128
#define H3    384
#define LL    4
#define GG    512
#define SCAN_B 512
#define NBLK  ((NN + SCAN_B - 1) / SCAN_B)

// ---------------- device scratch ----------------
__device__ float g_h0[NPAD * HH];
__device__ float g_h1[NPAD * HH];
__device__ float g_agg[NPAD * HH];
__device__ float g_cl[LL * HH * H3];
__device__ __nv_bfloat16 g_clT_hi[LL * H3 * HH];
__device__ __nv_bfloat16 g_clT_lo[LL * H3 * HH];
__device__ __nv_bfloat16 g_whh_hi[H3 * HH];
__device__ __nv_bfloat16 g_whh_lo[H3 * HH];
__device__ int   g_deg[NN];
__device__ int   g_rowptr[NN];
__device__ int   g_cursor[NN];
__device__ int   g_csr[EE];
__device__ int   g_bsums[NBLK];
__device__ float g_mu_all[GG];
__device__ float g_sig_all[GG];

__device__ __forceinline__ float sigmoidf_(float v) {
    return 1.0f / (1.0f + expf(-v));
}

__device__ __forceinline__ void mma16816(float* d, const uint32_t* a, const uint32_t* b) {
    asm volatile(
        "mma.sync.aligned.m16n8k16.row.col.f32.bf16.bf16.f32 {%0,%1,%2,%3}, {%4,%5,%6,%7}, {%8,%9}, {%0,%1,%2,%3};"
        : "+f"(d[0]), "+f"(d[1]), "+f"(d[2]), "+f"(d[3])
        : "r"(a[0]), "r"(a[1]), "r"(a[2]), "r"(a[3]), "r"(b[0]), "r"(b[1]));
}

// swizzled smem: row r (pitch 256B), 16B chunk ch stored at (ch ^ (r&7))
__device__ __forceinline__ uint32_t lds_frag(const char* base, int r, int kch, int t) {
    return *(const uint32_t*)(base + r * 256 + (((kch) ^ (r & 7)) << 4) + t * 4);
}

__device__ __forceinline__ uint32_t pack_bf2(float a, float b) {
    __nv_bfloat162 v;
    v.x = __float2bfloat16(a);
    v.y = __float2bfloat16(b);
    return *(uint32_t*)&v;
}

// ---------------- CSR build ----------------
__global__ void zero_deg_kernel() {
    int i = blockIdx.x * blockDim.x + threadIdx.x;
    if (i < NN) g_deg[i] = 0;
}
__global__ void zero_graph_kernel() {
    int i = threadIdx.x;
    if (i < GG) { g_mu_all[i] = 0.0f; g_sig_all[i] = 0.0f; }
}
__global__ void count_deg_kernel(const int* __restrict__ dst) {
    int e = blockIdx.x * blockDim.x + threadIdx.x;
    if (e < EE) atomicAdd(&g_deg[dst[e]], 1);
}
__global__ void scan1_kernel() {
    __shared__ int s[SCAN_B];
    int i = blockIdx.x * SCAN_B + threadIdx.x;
    int v = (i < NN) ? g_deg[i] : 0;
    s[threadIdx.x] = v;
    __syncthreads();
    for (int off = 1; off < SCAN_B; off <<= 1) {
        int t = 0;
        if (threadIdx.x >= off) t = s[threadIdx.x - off];
        __syncthreads();
        s[threadIdx.x] += t;
        __syncthreads();
    }
    if (i < NN) g_rowptr[i] = s[threadIdx.x] - v;
    if (threadIdx.x == SCAN_B - 1) g_bsums[blockIdx.x] = s[SCAN_B - 1];
}
__global__ void scan2_kernel() {
    if (threadIdx.x == 0) {
        int run = 0;
        for (int b = 0; b < NBLK; b++) { int t = g_bsums[b]; g_bsums[b] = run; run += t; }
    }
}
__global__ void scan3_kernel() {
    int i = blockIdx.x * blockDim.x + threadIdx.x;
    if (i < NN) {
        int v = g_rowptr[i] + g_bsums[i / SCAN_B];
        g_rowptr[i] = v;
        g_cursor[i] = v;
    }
}
__global__ void fill_csr_kernel(const int* __restrict__ src, const int* __restrict__ dst) {
    int e = blockIdx.x * blockDim.x + threadIdx.x;
    if (e < EE) {
        int p = atomicAdd(&g_cursor[dst[e]], 1);
        g_csr[p] = src[e];
    }
}

// ---------------- lin0 ----------------
__global__ void lin0_kernel(const float* __restrict__ x, const float* __restrict__ w,
                            float* __restrict__ out_x1) {
    int local = threadIdx.x >> 6;
    int j     = threadIdx.x & 63;
    int node  = blockIdx.x * 4 + local;
    __shared__ float xs[4][FIN];
    if (node < NN && j < FIN) xs[local][j] = x[node * FIN + j];
    __syncthreads();
    if (node >= NN) return;
    float acc = 0.0f;
#pragma unroll
    for (int k = 0; k < FIN; k++) acc += xs[local][k] * w[k * EMB + j];
    float v = sigmoidf_(acc);
    out_x1[node * EMB + j] = v;
    g_h0[node * HH + j] = v;
    g_h0[node * HH + EMB + j] = 0.0f;
}

// ---------------- small fp32 GEMM (weight precompute only) ----------------
template <bool BT>
__global__ void gemm_kernel(const float* __restrict__ A, const float* __restrict__ B,
                            float* __restrict__ C, int M, int Ncol, int K) {
    const int BM = 64, BN = 64, BK = 16;
    __shared__ float As[BK][BM];
    __shared__ float Bs[BK][BN];
    int t  = threadIdx.x;
    int tx = t & 15, ty = t >> 4;
    int row0 = blockIdx.y * BM, col0 = blockIdx.x * BN;
    float acc[4][4] = {};
    for (int k0 = 0; k0 < K; k0 += BK) {
#pragma unroll
        for (int i = 0; i < 4; i++) {
            int idx = t + i * 256;
            int r = idx >> 4, c = idx & 15;
            int gr = row0 + r;
            As[c][r] = (gr < M) ? A[gr * K + k0 + c] : 0.0f;
        }
#pragma unroll
        for (int i = 0; i < 4; i++) {
            int idx = t + i * 256;
            if (BT) {
                int j = idx >> 4, c = idx & 15;
                Bs[c][j] = B[(col0 + j) * K + k0 + c];
            } else {
                int r = idx >> 6, j = idx & 63;
                Bs[r][j] = B[(k0 + r) * Ncol + col0 + j];
            }
        }
        __syncthreads();
#pragma unroll
        for (int k = 0; k < BK; k++) {
            float4 a4 = *(const float4*)&As[k][ty * 4];
            float4 b4 = *(const float4*)&Bs[k][tx * 4];
            float av[4]; float bv[4];
            av[0] = a4.x; av[1] = a4.y; av[2] = a4.z; av[3] = a4.w;
            bv[0] = b4.x; bv[1] = b4.y; bv[2] = b4.z; bv[3] = b4.w;
#pragma unroll
            for (int i = 0; i < 4; i++)
#pragma unroll
                for (int j = 0; j < 4; j++) acc[i][j] += av[i] * bv[j];
        }
        __syncthreads();
    }
#pragma unroll
    for (int i = 0; i < 4; i++) {
        int gr = row0 + ty * 4 + i;
        if (gr < M) {
#pragma unroll
            for (int j = 0; j < 4; j++) C[gr * Ncol + col0 + tx * 4 + j] = acc[i][j];
        }
    }
}

// ---------------- weight prep ----------------
__global__ void conv_cl_kernel() {
    int idx = blockIdx.x * blockDim.x + threadIdx.x;
    if (idx >= LL * H3 * HH) return;
    int l = idx / (H3 * HH);
    int rem = idx - l * H3 * HH;
    int n = rem >> 7, k = rem & 127;
    float v = g_cl[l * HH * H3 + k * H3 + n];
    __nv_bfloat16 hi = __float2bfloat16(v);
    g_clT_hi[idx] = hi;
    g_clT_lo[idx] = __float2bfloat16(v - __bfloat162float(hi));
}
__global__ void conv_whh_kernel(const float* __restrict__ w) {
    int idx = blockIdx.x * blockDim.x + threadIdx.x;
    if (idx >= H3 * HH) return;
    float v = w[idx];
    __nv_bfloat16 hi = __float2bfloat16(v);
    g_whh_hi[idx] = hi;
    g_whh_lo[idx] = __float2bfloat16(v - __bfloat162float(hi));
}

// ---------------- CSR gather aggregation: warp per node, fp32 float4, unroll 4 ----------------
__global__ void agg_kernel(const float* __restrict__ h) {
    int wid = threadIdx.x >> 5, lane = threadIdx.x & 31;
    int n = blockIdx.x * 8 + wid;
    if (n >= NN) return;
    int s0 = g_rowptr[n];
    int d  = g_deg[n];
    float4 acc; acc.x = 0.0f; acc.y = 0.0f; acc.z = 0.0f; acc.w = 0.0f;
    int e = 0;
    for (; e + 4 <= d; e += 4) {
        int s1 = g_csr[s0 + e];
        int s2 = g_csr[s0 + e + 1];
        int s3 = g_csr[s0 + e + 2];
        int s4 = g_csr[s0 + e + 3];
        float4 v1 = *(const float4*)&h[(size_t)s1 * HH + lane * 4];
        float4 v2 = *(const float4*)&h[(size_t)s2 * HH + lane * 4];
        float4 v3 = *(const float4*)&h[(size_t)s3 * HH + lane * 4];
        float4 v4 = *(const float4*)&h[(size_t)s4 * HH + lane * 4];
        acc.x += (v1.x + v2.x) + (v3.x + v4.x);
        acc.y += (v1.y + v2.y) + (v3.y + v4.y);
        acc.z += (v1.z + v2.z) + (v3.z + v4.z);
        acc.w += (v1.w + v2.w) + (v3.w + v4.w);
    }
    for (; e < d; e++) {
        int s1 = g_csr[s0 + e];
        float4 v1 = *(const float4*)&h[(size_t)s1 * HH + lane * 4];
        acc.x += v1.x; acc.y += v1.y; acc.z += v1.z; acc.w += v1.w;
    }
    *(float4*)&g_agg[(size_t)n * HH + lane * 4] = acc;
}

// ---------------- fully fused dual-GEMM + GRU layer kernel, 2 CTAs/SM ----------------
// Tile: 64 rows x 48 gate-cols (16 j-cols x 3 gates). gi and gh accumulated
// simultaneously in registers; GRU gates applied in epilogue. No gi/gh buffers.
// A operands read as fp32 (agg, h) and split to bf16 hi/lo inline in the loader.
// grid = (8, NPAD/64), 256 threads, smem 112KB -> 2 CTAs/SM.
#define FS_AG_HI  0
#define FS_AG_LO  16384
#define FS_AH_HI  32768
#define FS_AH_LO  49152
#define FS_BC_HI  65536
#define FS_BC_LO  77824
#define FS_BW_HI  90112
#define FS_BW_LO  102400
#define FS_SMEM   114688

__global__ void __launch_bounds__(256, 2)
fused_layer_kernel(const float* __restrict__ agg, const float* __restrict__ hcur,
                   const __nv_bfloat16* __restrict__ Bchi, const __nv_bfloat16* __restrict__ Bclo,
                   const __nv_bfloat16* __restrict__ Bwhi, const __nv_bfloat16* __restrict__ Bwlo,
                   const float* __restrict__ b_ih, const float* __restrict__ b_hh,
                   float* __restrict__ hout) {
    extern __shared__ __align__(16) char smem[];

    int tid = threadIdx.x;
    int wid = tid >> 5, lane = tid & 31;
    int g = lane >> 2, t = lane & 3;
    int rowg = wid & 3;          // 4 groups x 16 rows
    int colg = wid >> 2;         // 2 groups x 8 j-cols
    int row0 = blockIdx.y * 64;
    int j0 = blockIdx.x * 16;

    // A loader: fp32 -> bf16 hi/lo inline. 2048 chunk tasks (2 matrices x 64 rows x 16 chunks)
    for (int i = tid; i < 2048; i += 256) {
        int m = i >> 10;
        int rem = i & 1023;
        int r = rem >> 4, ch = rem & 15;
        const float* srcp = (m ? hcur : agg) + (size_t)(row0 + r) * 128 + ch * 8;
        float4 f0 = *(const float4*)srcp;
        float4 f1 = *(const float4*)(srcp + 4);
        uint32_t hi[4], lo[4];
        float e[8];
        e[0] = f0.x; e[1] = f0.y; e[2] = f0.z; e[3] = f0.w;
        e[4] = f1.x; e[5] = f1.y; e[6] = f1.z; e[7] = f1.w;
        float r8[8];
#pragma unroll
        for (int q = 0; q < 8; q++) {
            __nv_bfloat16 hb = __float2bfloat16(e[q]);
            r8[q] = e[q] - __bfloat162float(hb);
        }
        hi[0] = pack_bf2(e[0], e[1]); hi[1] = pack_bf2(e[2], e[3]);
        hi[2] = pack_bf2(e[4], e[5]); hi[3] = pack_bf2(e[6], e[7]);
        lo[0] = pack_bf2(r8[0], r8[1]); lo[1] = pack_bf2(r8[2], r8[3]);
        lo[2] = pack_bf2(r8[4], r8[5]); lo[3] = pack_bf2(r8[6], r8[7]);
        int dstoff = r * 256 + ((ch ^ (r & 7)) << 4);
        int hbase = m ? FS_AH_HI : FS_AG_HI;
        int lbase = m ? FS_AH_LO : FS_AG_LO;
        *(uint4*)(smem + hbase + dstoff) = make_uint4(hi[0], hi[1], hi[2], hi[3]);
        *(uint4*)(smem + lbase + dstoff) = make_uint4(lo[0], lo[1], lo[2], lo[3]);
    }
    // B loader: 768 chunk tasks per array, 4 arrays
    for (int i = tid; i < 768; i += 256) {
        int br = i >> 4, ch = i & 15;
        int n = (br >> 4) * 128 + j0 + (br & 15);
        size_t goff = (size_t)n * 128 + ch * 8;
        int dstoff = br * 256 + ((ch ^ (br & 7)) << 4);
        *(uint4*)(smem + FS_BC_HI + dstoff) = *(const uint4*)&Bchi[goff];
        *(uint4*)(smem + FS_BC_LO + dstoff) = *(const uint4*)&Bclo[goff];
        *(uint4*)(smem + FS_BW_HI + dstoff) = *(const uint4*)&Bwhi[goff];
        *(uint4*)(smem + FS_BW_LO + dstoff) = *(const uint4*)&Bwlo[goff];
    }
    __syncthreads();

    float acc_gi[3][4];
    float acc_gh[3][4];
#pragma unroll
    for (int g3 = 0; g3 < 3; g3++)
#pragma unroll
        for (int q = 0; q < 4; q++) { acc_gi[g3][q] = 0.0f; acc_gh[g3][q] = 0.0f; }

    int r1 = rowg * 16 + g;
    int r2 = r1 + 8;

#pragma unroll
    for (int ks = 0; ks < 8; ks++) {
        uint32_t agh[4], agl[4], ahh[4], ahl[4];
        agh[0] = lds_frag(smem + FS_AG_HI, r1, 2 * ks, t);
        agh[1] = lds_frag(smem + FS_AG_HI, r2, 2 * ks, t);
        agh[2] = lds_frag(smem + FS_AG_HI, r1, 2 * ks + 1, t);
        agh[3] = lds_frag(smem + FS_AG_HI, r2, 2 * ks + 1, t);
        agl[0] = lds_frag(smem + FS_AG_LO, r1, 2 * ks, t);
        agl[1] = lds_frag(smem + FS_AG_LO, r2, 2 * ks, t);
        agl[2] = lds_frag(smem + FS_AG_LO, r1, 2 * ks + 1, t);
        agl[3] = lds_frag(smem + FS_AG_LO, r2, 2 * ks + 1, t);
        ahh[0] = lds_frag(smem + FS_AH_HI, r1, 2 * ks, t);
        ahh[1] = lds_frag(smem + FS_AH_HI, r2, 2 * ks, t);
        ahh[2] = lds_frag(smem + FS_AH_HI, r1, 2 * ks + 1, t);
        ahh[3] = lds_frag(smem + FS_AH_HI, r2, 2 * ks + 1, t);
        ahl[0] = lds_frag(smem + FS_AH_LO, r1, 2 * ks, t);
        ahl[1] = lds_frag(smem + FS_AH_LO, r2, 2 * ks, t);
        ahl[2] = lds_frag(smem + FS_AH_LO, r1, 2 * ks + 1, t);
        ahl[3] = lds_frag(smem + FS_AH_LO, r2, 2 * ks + 1, t);
#pragma unroll
        for (int g3 = 0; g3 < 3; g3++) {
            int br = g3 * 16 + colg * 8 + g;
            uint32_t bch[2], bcl[2], bwh[2], bwl[2];
            bch[0] = lds_frag(smem + FS_BC_HI, br, 2 * ks, t);
            bch[1] = lds_frag(smem + FS_BC_HI, br, 2 * ks + 1, t);
            bcl[0] = lds_frag(smem + FS_BC_LO, br, 2 * ks, t);
            bcl[1] = lds_frag(smem + FS_BC_LO, br, 2 * ks + 1, t);
            bwh[0] = lds_frag(smem + FS_BW_HI, br, 2 * ks, t);
            bwh[1] = lds_frag(smem + FS_BW_HI, br, 2 * ks + 1, t);
            bwl[0] = lds_frag(smem + FS_BW_LO, br, 2 * ks, t);
            bwl[1] = lds_frag(smem + FS_BW_LO, br, 2 * ks + 1, t);
            mma16816(acc_gi[g3], agh, bch);
            mma16816(acc_gi[g3], agh, bcl);
            mma16816(acc_gi[g3], agl, bch);
            mma16816(acc_gh[g3], ahh, bwh);
            mma16816(acc_gh[g3], ahh, bwl);
            mma16816(acc_gh[g3], ahl, bwh);
        }
    }

    // epilogue: GRU gates from registers
    int rbase = row0 + rowg * 16 + g;
    int jj = j0 + colg * 8 + t * 2;
    float2 bihr = *(const float2*)&b_ih[jj];
    float2 bihz = *(const float2*)&b_ih[128 + jj];
    float2 bihn = *(const float2*)&b_ih[256 + jj];
    float2 bhhr = *(const float2*)&b_hh[jj];
    float2 bhhz = *(const float2*)&b_hh[128 + jj];
    float2 bhhn = *(const float2*)&b_hh[256 + jj];
#pragma unroll
    for (int q = 0; q < 2; q++) {
        int rr = rbase + q * 8;
        float2 hp = *(const float2*)&hcur[(size_t)rr * HH + jj];
        float hn[2];
#pragma unroll
        for (int c = 0; c < 2; c++) {
            float gir = acc_gi[0][q * 2 + c];
            float giz = acc_gi[1][q * 2 + c];
            float gin = acc_gi[2][q * 2 + c];
            float ghr = acc_gh[0][q * 2 + c];
            float ghz = acc_gh[1][q * 2 + c];
            float ghn = acc_gh[2][q * 2 + c];
            float bir = (c == 0) ? bihr.x : bihr.y;
            float biz = (c == 0) ? bihz.x : bihz.y;
            float bin = (c == 0) ? bihn.x : bihn.y;
            float bhr = (c == 0) ? bhhr.x : bhhr.y;
            float bhz = (c == 0) ? bhhz.x : bhhz.y;
            float bhn = (c == 0) ? bhhn.x : bhhn.y;
            float hpc = (c == 0) ? hp.x : hp.y;
            float rv = sigmoidf_(gir + bir + ghr + bhr);
            float zv = sigmoidf_(giz + biz + ghz + bhz);
            float nv = tanhf(gin + bin + rv * (ghn + bhn));
            hn[c] = (1.0f - zv) * nv + zv * hpc;
        }
        float2 ho; ho.x = hn[0]; ho.y = hn[1];
        *(float2*)&hout[(size_t)rr * HH + jj] = ho;
    }
}

// ---------------- readout ----------------
__global__ void readout_kernel(const float* __restrict__ l1w, const float* __restrict__ l1b,
                               const float* __restrict__ l2w, const float* __restrict__ l2b,
                               const int* __restrict__ batch, const float* __restrict__ h,
                               float* __restrict__ out_mu, float* __restrict__ out_sigma) {
    int gt = blockIdx.x * blockDim.x + threadIdx.x;
    int n = gt >> 5;
    int lane = gt & 31;
    if (n >= NN) return;
    float s1 = 0.0f, s2 = 0.0f;
#pragma unroll
    for (int k = lane; k < HH; k += 32) {
        float v = fmaxf(h[(size_t)n * HH + k], 0.0f);
        s1 += v * l1w[k];
        s2 += v * l2w[k];
    }
#pragma unroll
    for (int o = 16; o; o >>= 1) {
        s1 += __shfl_down_sync(0xffffffffu, s1, o);
        s2 += __shfl_down_sync(0xffffffffu, s2, o);
    }
    if (lane == 0) {
        float mu = s1 + l1b[0];
        float sp = s2 + l2b[0];
        float sigma = fmaxf(sp, 0.0f) + log1pf(expf(-fabsf(sp)));
        out_mu[n] = mu;
        out_sigma[n] = sigma;
        atomicAdd(&g_mu_all[batch[n]], mu);
        atomicAdd(&g_sig_all[batch[n]], sigma);
    }
}

__global__ void correct_kernel(const int* __restrict__ batch,
                               const float* __restrict__ out_mu, const float* __restrict__ out_sigma,
                               float* __restrict__ out_mu_c) {
    int n = blockIdx.x * blockDim.x + threadIdx.x;
    if (n >= NN) return;
    int b = batch[n];
    out_mu_c[n] = out_mu[n] - g_mu_all[b] * (out_sigma[n] / g_sig_all[b]);
}

// ---------------- launch ----------------
extern "C" void kernel_launch(void* const* d_in, const int* in_sizes, int n_in,
                              void* d_out, int out_size) {
    const float* x      = (const float*)d_in[0];
    const int*   edge   = (const int*)d_in[1];
    const int*   batch  = (const int*)d_in[2];
    const float* lin0_w = (const float*)d_in[3];
    const float* ggc_w  = (const float*)d_in[4];
    const float* w_ih   = (const float*)d_in[5];
    const float* w_hh   = (const float*)d_in[6];
    const float* b_ih   = (const float*)d_in[7];
    const float* b_hh   = (const float*)d_in[8];
    const float* l1w    = (const float*)d_in[9];
    const float* l1b    = (const float*)d_in[10];
    const float* l2w    = (const float*)d_in[11];
    const float* l2b    = (const float*)d_in[12];

    float* out       = (float*)d_out;
    float* out_mu_c  = out;
    float* out_x1    = out + NN;
    float* out_sigma = out + NN + NN * EMB;
    float* out_mu    = out + NN + NN * EMB + NN;

    const int* src = edge;
    const int* dst = edge + EE;

    float *ph0, *ph1, *pagg, *pcl;
    __nv_bfloat16 *pclThi, *pclTlo, *pwhhhi, *pwhhlo;
    cudaGetSymbolAddress((void**)&ph0,    g_h0);
    cudaGetSymbolAddress((void**)&ph1,    g_h1);
    cudaGetSymbolAddress((void**)&pagg,   g_agg);
    cudaGetSymbolAddress((void**)&pcl,    g_cl);
    cudaGetSymbolAddress((void**)&pclThi, g_clT_hi);
    cudaGetSymbolAddress((void**)&pclTlo, g_clT_lo);
    cudaGetSymbolAddress((void**)&pwhhhi, g_whh_hi);
    cudaGetSymbolAddress((void**)&pwhhlo, g_whh_lo);

    cudaFuncSetAttribute(fused_layer_kernel, cudaFuncAttributeMaxDynamicSharedMemorySize, FS_SMEM);

    zero_deg_kernel<<<(NN + 255) / 256, 256>>>();
    zero_graph_kernel<<<1, GG>>>();
    count_deg_kernel<<<(EE + 255) / 256, 256>>>(dst);
    scan1_kernel<<<NBLK, SCAN_B>>>();
    scan2_kernel<<<1, 32>>>();
    scan3_kernel<<<(NN + 255) / 256, 256>>>();
    fill_csr_kernel<<<(EE + 255) / 256, 256>>>(src, dst);

    lin0_kernel<<<(NN + 3) / 4, 256>>>(x, lin0_w, out_x1);

    {
        dim3 gcl((H3 + 63) / 64, (HH + 63) / 64);
        for (int l = 0; l < LL; l++)
            gemm_kernel<true><<<gcl, 256>>>(ggc_w + l * HH * HH, w_ih, pcl + l * HH * H3, HH, H3, HH);
        conv_cl_kernel<<<(LL * H3 * HH + 255) / 256, 256>>>();
        conv_whh_kernel<<<(H3 * HH + 255) / 256, 256>>>(w_hh);
    }

    dim3 ggrid(8, NPAD / 64);
    for (int l = 0; l < LL; l++) {
        const float* hcur = (l & 1) ? ph1 : ph0;
        float* hnext      = (l & 1) ? ph0 : ph1;

        agg_kernel<<<(NN + 7) / 8, 256>>>(hcur);
        fused_layer_kernel<<<ggrid, 256, FS_SMEM>>>(pagg, hcur,
                                                    pclThi + l * H3 * HH, pclTlo + l * H3 * HH,
                                                    pwhhhi, pwhhlo,
                                                    b_ih, b_hh, hnext);
    }

    readout_kernel<<<(NN * 32 + 255) / 256, 256>>>(l1w, l1b, l2w, l2b, batch, ph0, out_mu, out_sigma);
    correct_kernel<<<(NN + 255) / 256, 256>>>(batch, out_mu, out_sigma, out_mu_c);
}